// round 6
// baseline (speedup 1.0000x reference)
#include <cuda_runtime.h>
#include <cuda_bf16.h>
#include <cooperative_groups.h>

namespace cg = cooperative_groups;

#define NP 8192
#define GD 48                      // cells per dimension
#define NCELLS (GD * GD * GD)      // 110592
#define CAP 20                     // slots per cell (Poisson(4.2) -> P(>20) ~ 1e-9)
#define CELL_INV 5.0f              // 1 / 0.2
#define GMIN 4.8f                  // grid covers [-4.8, 4.8); outliers clamp (safe)
#define INV_H 10.0f
#define EPS 1e-10f

#define NBLK 592                   // 4 blocks/SM * 148 SMs
#define NTHR 256

// 8 / (PI * H^3) — matches reference constant
__device__ __constant__ float kNorm = (float)(8.0 / (3.14159265 * 0.001));

// Invariant: d_cnt is all-zero on entry to every kernel_launch call
// (zero at module load via .bss; cleanup phase restores it each call).
__device__ int    d_cnt[NCELLS];
__device__ float4 d_slot[NCELLS * CAP];

__device__ __forceinline__ int cell_coord(float v) {
    int c = __float2int_rd((v + GMIN) * CELL_INV);
    return min(max(c, 0), GD - 1);
}

__device__ __forceinline__ int cell_of(const float* __restrict__ pos, int i,
                                       float& x, float& y, float& z) {
    x = pos[3 * i + 0]; y = pos[3 * i + 1]; z = pos[3 * i + 2];
    return (cell_coord(z) * GD + cell_coord(y)) * GD + cell_coord(x);
}

__device__ __forceinline__ void build_one(const float* __restrict__ pos, int i) {
    float x, y, z;
    int c = cell_of(pos, i, x, y, z);
    int slot = atomicAdd(&d_cnt[c], 1);
    if (slot < CAP) d_slot[c * CAP + slot] = make_float4(x, y, z, 0.0f);
}

// Warp-per-particle query: lane k < 27 owns stencil cell k.
__device__ __forceinline__ void query_one(const float* __restrict__ pos,
                                          float* __restrict__ out,
                                          int i, int lane)
{
    const float xi = pos[3 * i + 0];
    const float yi = pos[3 * i + 1];
    const float zi = pos[3 * i + 2];
    const int ix = cell_coord(xi), iy = cell_coord(yi), iz = cell_coord(zi);

    float acc = 0.0f;
    if (lane < 27) {
        int dz = lane / 9, rem = lane - dz * 9;
        int dy = rem / 3,  dx  = rem - dy * 3;
        int cx = ix + dx - 1, cy = iy + dy - 1, cz = iz + dz - 1;
        if ((unsigned)cx < GD && (unsigned)cy < GD && (unsigned)cz < GD) {
            int c = (cz * GD + cy) * GD + cx;
            int n = min(d_cnt[c], CAP);
            const float4* sp = &d_slot[c * CAP];
            for (int e = 0; e < n; e++) {
                float4 p = sp[e];
                float ddx = p.x - xi;
                float ddy = p.y - yi;
                float ddz = p.z - zi;
                float r2 = fmaf(ddx, ddx, fmaf(ddy, ddy, fmaf(ddz, ddz, EPS)));
                float r;
                asm("sqrt.approx.f32 %0, %1;" : "=f"(r) : "f"(r2));
                float q   = r * INV_H;
                float qm1 = q - 1.0f;
                float wi  = fmaf(q * q * 6.0f, qm1, 1.0f);   // 1 - 6q^2 + 6q^3
                float wo  = -2.0f * qm1 * qm1 * qm1;         // 2(1-q)^3
                float w   = (q <= 0.5f) ? wi : wo;
                acc += (q <= 1.0f) ? w : 0.0f;
            }
        }
    }
    #pragma unroll
    for (int off = 16; off > 0; off >>= 1)
        acc += __shfl_xor_sync(0xFFFFFFFFu, acc, off);
    if (lane == 0) out[i] = acc * kNorm;
}

__device__ __forceinline__ void cleanup_one(const float* __restrict__ pos, int i) {
    float x, y, z;
    int c = cell_of(pos, i, x, y, z);
    d_cnt[c] = 0;   // racing identical stores: benign
}

// ---------------- fused cooperative kernel ----------------
__global__ void __launch_bounds__(NTHR, 4) fused_kernel(
    const float* __restrict__ pos, float* __restrict__ out)
{
    cg::grid_group grid = cg::this_grid();
    const int t     = blockIdx.x * NTHR + threadIdx.x;
    const int total = gridDim.x * NTHR;
    const int lane  = t & 31;
    const int wid   = t >> 5;
    const int nw    = total >> 5;

    for (int i = t; i < NP; i += total) build_one(pos, i);
    grid.sync();
    for (int i = wid; i < NP; i += nw) query_one(pos, out, i, lane);
    grid.sync();
    for (int i = t; i < NP; i += total) cleanup_one(pos, i);
}

// ---------------- fallback path (3 small kernels) ----------------
__global__ void __launch_bounds__(256) build_kernel(const float* __restrict__ pos) {
    int i = blockIdx.x * blockDim.x + threadIdx.x;
    if (i < NP) build_one(pos, i);
}

__global__ void __launch_bounds__(256) query_kernel(
    const float* __restrict__ pos, float* __restrict__ out)
{
    int t = blockIdx.x * blockDim.x + threadIdx.x;
    query_one(pos, out, t >> 5, t & 31);
}

__global__ void __launch_bounds__(256) cleanup_kernel(const float* __restrict__ pos) {
    int i = blockIdx.x * blockDim.x + threadIdx.x;
    if (i < NP) cleanup_one(pos, i);
}

extern "C" void kernel_launch(void* const* d_in, const int* in_sizes, int n_in,
                              void* d_out, int out_size)
{
    const float* pos = (const float*)d_in[0];
    float* out = (float*)d_out;
    (void)in_sizes; (void)n_in; (void)out_size;

    void* args[] = { (void*)&pos, (void*)&out };
    cudaError_t e = cudaLaunchCooperativeKernel(
        (const void*)fused_kernel, dim3(NBLK), dim3(NTHR), args, 0, (cudaStream_t)0);

    if (e != cudaSuccess) {
        (void)cudaGetLastError();   // clear sticky error, take 3-kernel path
        build_kernel<<<NP / 256, 256>>>(pos);
        query_kernel<<<NP * 32 / 256, 256>>>(pos, out);
        cleanup_kernel<<<NP / 256, 256>>>(pos);
    }
}